// round 11
// baseline (speedup 1.0000x reference)
#include <cuda_runtime.h>
#include <cuda_fp16.h>
#include <cstdint>

// Problem constants
#define N_TOK  8192
#define IN_F   4096
#define OUT_F  4096
#define BLK    64
#define KBLK   16
#define TM     256          // token tile
#define NSTG   3            // A pipeline depth

// SMEM layout (bytes): W resident + 3 A buffers + staging
#define W_BYTES   (KBLK * BLK * BLK * 2)   // 131072
#define A_BYTES   (TM * BLK * 2)           // 32768 per stage (swizzled, no pad)
#define OFF_A     W_BYTES                  // 131072
#define OFF_COLS  (OFF_A + NSTG * A_BYTES) // 229376
#define OFF_BIAS  (OFF_COLS + 64)          // 229440
#define SMEM_BYTES (OFF_BIAS + 256)        // 229696

// fp16 copies of x and w (converted each call)
__device__ __align__(16) __half g_xh[(size_t)N_TOK * IN_F];
__device__ __align__(16) __half g_wh[(size_t)BLK * KBLK * BLK * BLK];

__global__ void conv_all(const float4* __restrict__ x, const float4* __restrict__ w,
                         uint2* __restrict__ xh, uint2* __restrict__ wh,
                         int nx4, int nw4) {
    int i = blockIdx.x * blockDim.x + threadIdx.x;
    float4 v;
    uint2* o;
    if (i < nx4)            { v = x[i];       o = xh + i; }
    else if (i < nx4 + nw4) { v = w[i - nx4]; o = wh + (i - nx4); }
    else return;
    __half2 h0 = __floats2half2_rn(v.x, v.y);
    __half2 h1 = __floats2half2_rn(v.z, v.w);
    uint2 r; r.x = *(uint32_t*)&h0; r.y = *(uint32_t*)&h1;
    *o = r;
}

__device__ __forceinline__ void cp_async16(uint32_t saddr, const void* gptr) {
    asm volatile("cp.async.cg.shared.global [%0], [%1], 16;\n" :: "r"(saddr), "l"(gptr));
}
__device__ __forceinline__ void ldsm_x4(uint32_t& r0, uint32_t& r1, uint32_t& r2, uint32_t& r3,
                                        uint32_t saddr) {
    asm volatile("ldmatrix.sync.aligned.m8n8.x4.shared.b16 {%0,%1,%2,%3}, [%4];\n"
                 : "=r"(r0), "=r"(r1), "=r"(r2), "=r"(r3) : "r"(saddr));
}
__device__ __forceinline__ uint32_t sw128(uint32_t b) { return b ^ ((b >> 3) & 0x70); }

// load all fragments for k-step s into slot c (kxa/kxb are the per-lane
// swizzle-corrected k-step byte offsets)
#define LD_FRAGS(c, s)                                                             \
    do {                                                                           \
        _Pragma("unroll")                                                          \
        for (int _i = 0; _i < 4; ++_i)                                             \
            ldsm_x4(a[c][_i][0], a[c][_i][1], a[c][_i][2], a[c][_i][3],            \
                    aad[_i] + kxa[s]);                                             \
        _Pragma("unroll")                                                          \
        for (int _jp = 0; _jp < 2; ++_jp)                                          \
            ldsm_x4(b[c][2*_jp][0], b[c][2*_jp][1], b[c][2*_jp+1][0],              \
                    b[c][2*_jp+1][1], bad[_jp] + kxb[s]);                          \
    } while (0)

__global__ __launch_bounds__(256, 1)
void bsl_f16_kernel(const float* __restrict__ bias,
                    const int*   __restrict__ col_idx,
                    float* __restrict__ out)
{
    extern __shared__ char smem[];
    const uint32_t sb0 = (uint32_t)__cvta_generic_to_shared(smem);
    const int tid  = threadIdx.x;
    const int lane = tid & 31;
    const int warp = tid >> 5;
    const int wm   = warp & 3;                 // 4 warps along M -> 64 rows each
    const int wn   = warp >> 2;                // 2 warps along N -> 32 cols each
    const int rb   = blockIdx.x >> 1;          // fixed output row-block
    const int half = blockIdx.x & 1;           // token-tile half (16 tiles each)
    const int n0   = rb * BLK;
    int* s_cols    = (int*)(smem + OFF_COLS);
    float* s_bias  = (float*)(smem + OFF_BIAS);

    // ---- prologue: stage cols/bias, load resident W (128KB, swizzled) ----
    if (tid < KBLK) s_cols[tid] = __ldg(&col_idx[rb * KBLK + tid]) * BLK;
    if (tid < BLK)  s_bias[tid] = bias[n0 + tid];
    {
        const uint32_t swt = sw128((uint32_t)tid * 16);
        const __half* ws = g_wh + (size_t)rb * (KBLK * BLK * BLK) + tid * 8;
        #pragma unroll
        for (int p = 0; p < 32; ++p)
            cp_async16(sb0 + p * 4096 + swt, ws + (size_t)p * 2048);
        asm volatile("cp.async.commit_group;\n");
    }
    asm volatile("cp.async.wait_group 0;\n");
    __syncthreads();                            // W + cols + bias visible

    // ---- A stage loader: stage st = tile*16 + kb; buffer = st % 3 ----
    const int lrow = tid >> 3;                  // 0..31
    const int lch8 = (tid & 7) * 8;             // halves
    const uint32_t a_swt = sw128((uint32_t)(lrow * 128 + (tid & 7) * 16));
    auto issue_stage = [&](int st, int buf) {
        const int tile = st >> 4, kb = st & 15;
        const int m0 = (half * 16 + tile) * TM;
        const int col = s_cols[kb];
        const __half* xg = g_xh + (size_t)(m0 + lrow) * IN_F + col + lch8;
        const uint32_t dst = sb0 + OFF_A + buf * A_BYTES + a_swt;
        #pragma unroll
        for (int p = 0; p < 8; ++p)             // rows lrow + 32p
            cp_async16(dst + p * 4096, xg + (size_t)p * 32 * IN_F);
        asm volatile("cp.async.commit_group;\n");
    };

    issue_stage(0, 0);
    issue_stage(1, 1);

    // ---- per-lane fragment addressing with exact swizzle decomposition ----
    // sw128(row*128 + coff + s*32) = row*128 + (coff ^ m4) + ((s*32) ^ m56),
    // m4 = (row&1)<<4, m56 = (row&6)<<4  (coff bit4; s*32 bits 5-6: disjoint)
    const int a_row  = lane & 15;
    const int a_coff = (lane >> 4) * 16;        // bytes
    const int b_row  = ((lane >> 4) << 3) + (lane & 7);
    const int b_coff = ((lane >> 3) & 1) * 16;  // bytes
    const uint32_t a_m4  = (uint32_t)(a_row & 1) << 4;
    const uint32_t a_m56 = (uint32_t)(a_row & 6) << 4;
    const uint32_t b_m4  = (uint32_t)(b_row & 1) << 4;
    const uint32_t b_m56 = (uint32_t)(b_row & 6) << 4;
    uint32_t kxa[4], kxb[4];
    #pragma unroll
    for (int s = 0; s < 4; ++s) {
        kxa[s] = ((uint32_t)(s * 32)) ^ a_m56;
        kxb[s] = ((uint32_t)(s * 32)) ^ b_m56;
    }
    uint32_t abase0[4], bbase0[2];
    #pragma unroll
    for (int i = 0; i < 4; ++i)
        abase0[i] = sb0 + OFF_A + (uint32_t)(wm * 64 + i * 16 + a_row) * 128 +
                    ((uint32_t)a_coff ^ a_m4);
    #pragma unroll
    for (int jp = 0; jp < 2; ++jp)
        bbase0[jp] = sb0 + (uint32_t)(wn * 32 + jp * 16 + b_row) * 128 +
                     ((uint32_t)b_coff ^ b_m4);

    float acc[4][4][4];
    #pragma unroll
    for (int i = 0; i < 4; ++i)
        #pragma unroll
        for (int j = 0; j < 4; ++j)
            #pragma unroll
            for (int r = 0; r < 4; ++r) acc[i][j][r] = 0.f;

    const int NST = 16 * KBLK;                  // 256 stages
    int cbuf = 0, ibuf = 2;
    for (int st = 0; st < NST; ++st) {
        if (st < NST - 1) asm volatile("cp.async.wait_group 1;\n");
        else              asm volatile("cp.async.wait_group 0;\n");
        __syncthreads();                        // stage st ready; all warps past st-1

        if (st + 2 < NST) {
            issue_stage(st + 2, ibuf);          // reuses buffer of stage st-1 (safe: sync above)
            if (++ibuf == NSTG) ibuf = 0;
        }

        const int kb = st & 15;
        uint32_t aad[4], bad[2];
        const uint32_t ao = cbuf * A_BYTES;
        const uint32_t bo = kb * 8192;
        #pragma unroll
        for (int i = 0; i < 4; ++i) aad[i] = abase0[i] + ao;
        #pragma unroll
        for (int jp = 0; jp < 2; ++jp) bad[jp] = bbase0[jp] + bo;
        if (++cbuf == NSTG) cbuf = 0;

        uint32_t a[2][4][4], b[2][4][2];
        LD_FRAGS(0, 0);
        #pragma unroll
        for (int s = 0; s < 4; ++s) {           // K=64, k16 per MMA
            const int c = s & 1;
            if (s < 3) LD_FRAGS(c ^ 1, s + 1);
            #pragma unroll
            for (int i = 0; i < 4; ++i)
                #pragma unroll
                for (int j = 0; j < 4; ++j) {
                    asm volatile(
                        "mma.sync.aligned.m16n8k16.row.col.f32.f16.f16.f32 "
                        "{%0,%1,%2,%3}, {%4,%5,%6,%7}, {%8,%9}, {%0,%1,%2,%3};\n"
                        : "+f"(acc[i][j][0]), "+f"(acc[i][j][1]),
                          "+f"(acc[i][j][2]), "+f"(acc[i][j][3])
                        : "r"(a[c][i][0]), "r"(a[c][i][1]), "r"(a[c][i][2]), "r"(a[c][i][3]),
                          "r"(b[c][j][0]), "r"(b[c][j][1]));
                }
        }

        if (kb == 15) {                         // tile done: epilogue + reset acc
            const int m0 = (half * 16 + (st >> 4)) * TM;
            const int qr = lane >> 2, ql = lane & 3;
            #pragma unroll
            for (int j = 0; j < 4; ++j) {
                const int col = wn * 32 + j * 8 + 2 * ql;
                const float2 bv = *(const float2*)(s_bias + col);
                #pragma unroll
                for (int i = 0; i < 4; ++i) {
                    const int row = m0 + wm * 64 + i * 16 + qr;
                    float2 v0 = { acc[i][j][0] + bv.x, acc[i][j][1] + bv.y };
                    *(float2*)(out + (size_t)row * OUT_F + n0 + col) = v0;
                    float2 v1 = { acc[i][j][2] + bv.x, acc[i][j][3] + bv.y };
                    *(float2*)(out + (size_t)(row + 8) * OUT_F + n0 + col) = v1;
                    acc[i][j][0] = acc[i][j][1] = acc[i][j][2] = acc[i][j][3] = 0.f;
                }
            }
        }
    }
}

extern "C" void kernel_launch(void* const* d_in, const int* in_sizes, int n_in,
                              void* d_out, int out_size)
{
    const float* x       = (const float*)d_in[0];
    const float* weight  = (const float*)d_in[1];
    const float* bias    = (const float*)d_in[2];
    // d_in[3] = row_idx (deterministic repeat(arange(64),16)) — unused
    const int*   col_idx = (const int*)d_in[4];
    float* out = (float*)d_out;

    __half* xh_p; cudaGetSymbolAddress((void**)&xh_p, g_xh);
    __half* wh_p; cudaGetSymbolAddress((void**)&wh_p, g_wh);
    const int nx4 = (N_TOK * IN_F) / 4;
    const int nw4 = (BLK * KBLK * BLK * BLK) / 4;
    conv_all<<<(nx4 + nw4) / 256, 256>>>((const float4*)x, (const float4*)weight,
                                         (uint2*)xh_p, (uint2*)wh_p, nx4, nw4);

    cudaFuncSetAttribute(bsl_f16_kernel,
                         cudaFuncAttributeMaxDynamicSharedMemorySize, SMEM_BYTES);
    bsl_f16_kernel<<<128, 256, SMEM_BYTES>>>(bias, col_idx, out);  // persistent: 2 CTAs/rb
}

// round 13
// speedup vs baseline: 1.0801x; 1.0801x over previous
#include <cuda_runtime.h>
#include <cuda_fp16.h>
#include <cstdint>

// Problem constants
#define N_TOK  8192
#define IN_F   4096
#define OUT_F  4096
#define BLK    64
#define KBLK   16
#define TM     128    // token tile per CTA (32x32 warp tiles, low regs -> 3 CTAs/SM)
#define LDH    72     // halves per smem row (144B stride -> conflict-free ldmatrix)
#define ABYT   (TM * LDH * 2)     // 18432
#define BBYT   (BLK * LDH * 2)    // 9216
#define BUFB   (ABYT + BBYT)      // 27648
#define SMEM_BYTES (2 * BUFB)     // 55296 (x3 CTAs = 166KB/SM)

// fp16 copies of x and w (converted each call)
__device__ __align__(16) __half g_xh[(size_t)N_TOK * IN_F];
__device__ __align__(16) __half g_wh[(size_t)BLK * KBLK * BLK * BLK];

__global__ void conv_all(const float4* __restrict__ x, const float4* __restrict__ w,
                         uint2* __restrict__ xh, uint2* __restrict__ wh,
                         int nx4, int nw4) {
    int i = blockIdx.x * blockDim.x + threadIdx.x;
    float4 v;
    uint2* o;
    if (i < nx4)            { v = x[i];       o = xh + i; }
    else if (i < nx4 + nw4) { v = w[i - nx4]; o = wh + (i - nx4); }
    else return;
    __half2 h0 = __floats2half2_rn(v.x, v.y);
    __half2 h1 = __floats2half2_rn(v.z, v.w);
    uint2 r; r.x = *(uint32_t*)&h0; r.y = *(uint32_t*)&h1;
    *o = r;
}

__device__ __forceinline__ void cp_async16(uint32_t saddr, const void* gptr) {
    asm volatile("cp.async.cg.shared.global [%0], [%1], 16;\n" :: "r"(saddr), "l"(gptr));
}
__device__ __forceinline__ void ldsm_x4(uint32_t& r0, uint32_t& r1, uint32_t& r2, uint32_t& r3,
                                        uint32_t saddr) {
    asm volatile("ldmatrix.sync.aligned.m8n8.x4.shared.b16 {%0,%1,%2,%3}, [%4];\n"
                 : "=r"(r0), "=r"(r1), "=r"(r2), "=r"(r3) : "r"(saddr));
}

__global__ __launch_bounds__(256, 3)
void bsl_f16_kernel(const float* __restrict__ bias,
                    const int*   __restrict__ col_idx,
                    float* __restrict__ out)
{
    extern __shared__ char smem[];
    const uint32_t sb0 = (uint32_t)__cvta_generic_to_shared(smem);
    const int rb  = blockIdx.x;        // output row-block (fast index -> x L2 reuse)
    const int mti = blockIdx.y;
    const int m0  = mti * TM;
    const int n0  = rb * BLK;
    const int tid = threadIdx.x;

    const int lane = tid & 31;
    const int warp = tid >> 5;
    const int wm   = warp & 3;         // 4 warps along M -> 32 rows each
    const int wn   = warp >> 2;        // 2 warps along N -> 32 cols each
    const int qr   = lane >> 2;
    const int ql   = lane & 3;

    // ---- loader: fp16 tiles, 16B chunks ----
    const int lrow = tid >> 3;         // 0..31
    const int lchk = (tid & 7) * 8;    // half offset within row
    auto load_block = [&](int kb, int buf) {
        const int col = __ldg(&col_idx[rb * KBLK + kb]) * BLK;
        const uint32_t so = buf * BUFB;
        const __half* xg = g_xh + (size_t)(m0 + lrow) * IN_F + col + lchk;
        const uint32_t sa = sb0 + so + (lrow * LDH + lchk) * 2;
        #pragma unroll
        for (int p = 0; p < 4; ++p)
            cp_async16(sa + p * 32 * LDH * 2, xg + (size_t)p * 32 * IN_F);
        const __half* wg = g_wh + (size_t)(rb * KBLK + kb) * (BLK * BLK) + lrow * BLK + lchk;
        const uint32_t sw = sb0 + so + ABYT + (lrow * LDH + lchk) * 2;
        #pragma unroll
        for (int p = 0; p < 2; ++p)
            cp_async16(sw + p * 32 * LDH * 2, wg + p * 32 * BLK);
        asm volatile("cp.async.commit_group;\n");
    };

    float acc[2][4][4];
    #pragma unroll
    for (int i = 0; i < 2; ++i)
        #pragma unroll
        for (int j = 0; j < 4; ++j)
            #pragma unroll
            for (int r = 0; r < 4; ++r) acc[i][j][r] = 0.f;

    load_block(0, 0);

    // ldmatrix per-thread addressing (halves)
    const int a_row  = lane & 15;
    const int a_coff = (lane >> 4) * 8;
    const int b_row  = ((lane >> 4) << 3) + (lane & 7);
    const int b_coff = ((lane >> 3) & 1) * 8;

    for (int kb = 0; kb < KBLK; ++kb) {
        const int cur = kb & 1;
        asm volatile("cp.async.wait_group 0;\n");
        __syncthreads();                       // buffer 'cur' ready; prior reads of cur^1 done

        if (kb < KBLK - 1)
            load_block(kb + 1, cur ^ 1);       // overlaps the compute below

        const uint32_t so = cur * BUFB;
        uint32_t aaddr[2], baddr[2];
        #pragma unroll
        for (int i = 0; i < 2; ++i)
            aaddr[i] = sb0 + so + ((wm * 32 + i * 16 + a_row) * LDH + a_coff) * 2;
        #pragma unroll
        for (int jp = 0; jp < 2; ++jp)
            baddr[jp] = sb0 + so + ABYT + ((wn * 32 + jp * 16 + b_row) * LDH + b_coff) * 2;

        #pragma unroll
        for (int s = 0; s < 4; ++s) {          // K=64, 16 per MMA
            const uint32_t koff = s * 32;      // bytes (16 halves)
            uint32_t a[2][4], b[4][2];
            #pragma unroll
            for (int i = 0; i < 2; ++i)
                ldsm_x4(a[i][0], a[i][1], a[i][2], a[i][3], aaddr[i] + koff);
            #pragma unroll
            for (int jp = 0; jp < 2; ++jp)
                ldsm_x4(b[2 * jp][0], b[2 * jp][1], b[2 * jp + 1][0], b[2 * jp + 1][1],
                        baddr[jp] + koff);
            #pragma unroll
            for (int i = 0; i < 2; ++i)
                #pragma unroll
                for (int j = 0; j < 4; ++j) {
                    asm volatile(
                        "mma.sync.aligned.m16n8k16.row.col.f32.f16.f16.f32 "
                        "{%0,%1,%2,%3}, {%4,%5,%6,%7}, {%8,%9}, {%0,%1,%2,%3};\n"
                        : "+f"(acc[i][j][0]), "+f"(acc[i][j][1]),
                          "+f"(acc[i][j][2]), "+f"(acc[i][j][3])
                        : "r"(a[i][0]), "r"(a[i][1]), "r"(a[i][2]), "r"(a[i][3]),
                          "r"(b[j][0]), "r"(b[j][1]));
                }
        }
    }

    // ---- epilogue: bias add + float2 stores ----
    #pragma unroll
    for (int j = 0; j < 4; ++j) {
        const int col = n0 + wn * 32 + j * 8 + 2 * ql;
        const float2 bv = *(const float2*)(bias + col);
        #pragma unroll
        for (int i = 0; i < 2; ++i) {
            const int row = m0 + wm * 32 + i * 16 + qr;
            float2 v0 = { acc[i][j][0] + bv.x, acc[i][j][1] + bv.y };
            *(float2*)(out + (size_t)row * OUT_F + col) = v0;
            float2 v1 = { acc[i][j][2] + bv.x, acc[i][j][3] + bv.y };
            *(float2*)(out + (size_t)(row + 8) * OUT_F + col) = v1;
        }
    }
}

extern "C" void kernel_launch(void* const* d_in, const int* in_sizes, int n_in,
                              void* d_out, int out_size)
{
    const float* x       = (const float*)d_in[0];
    const float* weight  = (const float*)d_in[1];
    const float* bias    = (const float*)d_in[2];
    // d_in[3] = row_idx (deterministic repeat(arange(64),16)) — unused
    const int*   col_idx = (const int*)d_in[4];
    float* out = (float*)d_out;

    __half* xh_p; cudaGetSymbolAddress((void**)&xh_p, g_xh);
    __half* wh_p; cudaGetSymbolAddress((void**)&wh_p, g_wh);
    const int nx4 = (N_TOK * IN_F) / 4;
    const int nw4 = (BLK * KBLK * BLK * BLK) / 4;
    conv_all<<<(nx4 + nw4) / 256, 256>>>((const float4*)x, (const float4*)weight,
                                         (uint2*)xh_p, (uint2*)wh_p, nx4, nw4);

    cudaFuncSetAttribute(bsl_f16_kernel,
                         cudaFuncAttributeMaxDynamicSharedMemorySize, SMEM_BYTES);
    dim3 grid(OUT_F / BLK, N_TOK / TM);   // (64, 64); rb fastest -> x L2 reuse
    bsl_f16_kernel<<<grid, 256, SMEM_BYTES>>>(bias, col_idx, out);
}

// round 15
// speedup vs baseline: 1.1366x; 1.0523x over previous
#include <cuda_runtime.h>
#include <cuda_fp16.h>
#include <cstdint>

// Problem constants
#define N_TOK  8192
#define IN_F   4096
#define OUT_F  4096
#define BLK    64
#define KBLK   16
#define TM     128    // token tile per CTA (32x32 warp tiles)
#define LDH    72     // halves per smem row (144B stride -> conflict-free ldmatrix)
#define ABYT   (TM * LDH * 2)     // 18432
#define BBYT   (BLK * LDH * 2)    // 9216
#define BUFB   (ABYT + BBYT)      // 27648
#define SMEM_BYTES (2 * BUFB)     // 55296 (x4 CTAs = 221KB/SM)

// fp16 copies of x and w (converted each call)
__device__ __align__(16) __half g_xh[(size_t)N_TOK * IN_F];
__device__ __align__(16) __half g_wh[(size_t)BLK * KBLK * BLK * BLK];

__global__ void conv_all(const float4* __restrict__ x, const float4* __restrict__ w,
                         uint2* __restrict__ xh, uint2* __restrict__ wh,
                         int nx4, int nw4) {
    int i = blockIdx.x * blockDim.x + threadIdx.x;
    float4 v;
    uint2* o;
    if (i < nx4)            { v = x[i];       o = xh + i; }
    else if (i < nx4 + nw4) { v = w[i - nx4]; o = wh + (i - nx4); }
    else return;
    __half2 h0 = __floats2half2_rn(v.x, v.y);
    __half2 h1 = __floats2half2_rn(v.z, v.w);
    uint2 r; r.x = *(uint32_t*)&h0; r.y = *(uint32_t*)&h1;
    *o = r;
}

__device__ __forceinline__ void cp_async16(uint32_t saddr, const void* gptr) {
    asm volatile("cp.async.cg.shared.global [%0], [%1], 16;\n" :: "r"(saddr), "l"(gptr));
}
__device__ __forceinline__ void ldsm_x4(uint32_t& r0, uint32_t& r1, uint32_t& r2, uint32_t& r3,
                                        uint32_t saddr) {
    asm volatile("ldmatrix.sync.aligned.m8n8.x4.shared.b16 {%0,%1,%2,%3}, [%4];\n"
                 : "=r"(r0), "=r"(r1), "=r"(r2), "=r"(r3) : "r"(saddr));
}

__global__ __launch_bounds__(256, 4)
void bsl_f16_kernel(const float* __restrict__ bias,
                    const int*   __restrict__ col_idx,
                    float* __restrict__ out)
{
    extern __shared__ char smem[];
    const uint32_t sb0 = (uint32_t)__cvta_generic_to_shared(smem);
    const int rb  = blockIdx.x;        // output row-block (fast index -> x L2 reuse)
    const int m0  = blockIdx.y * TM;
    const int tid = threadIdx.x;

    const int lane = tid & 31;
    const int warp = tid >> 5;
    const int wm   = warp & 3;         // 4 warps along M -> 32 rows each
    const int wn   = warp >> 2;        // 2 warps along N -> 32 cols each

    // ---- loader: addresses recomputed per call (keeps live ranges tiny) ----
    auto load_block = [&](int kb, int buf) {
        const int lrow = tid >> 3;
        const int lchk = (tid & 7) * 8;
        const int col = __ldg(&col_idx[rb * KBLK + kb]) * BLK;
        const uint32_t so = buf * BUFB;
        const __half* xg = g_xh + (size_t)(m0 + lrow) * IN_F + col + lchk;
        const uint32_t sa = sb0 + so + (lrow * LDH + lchk) * 2;
        #pragma unroll
        for (int p = 0; p < 4; ++p)
            cp_async16(sa + p * 32 * LDH * 2, xg + (size_t)p * 32 * IN_F);
        const __half* wg = g_wh + (size_t)(rb * KBLK + kb) * (BLK * BLK) + lrow * BLK + lchk;
        const uint32_t sw = sb0 + so + ABYT + (lrow * LDH + lchk) * 2;
        #pragma unroll
        for (int p = 0; p < 2; ++p)
            cp_async16(sw + p * 32 * LDH * 2, wg + p * 32 * BLK);
        asm volatile("cp.async.commit_group;\n");
    };

    float acc[2][4][4];
    #pragma unroll
    for (int i = 0; i < 2; ++i)
        #pragma unroll
        for (int j = 0; j < 4; ++j)
            #pragma unroll
            for (int r = 0; r < 4; ++r) acc[i][j][r] = 0.f;

    load_block(0, 0);

    for (int kb = 0; kb < KBLK; ++kb) {
        const int cur = kb & 1;
        asm volatile("cp.async.wait_group 0;\n");
        __syncthreads();                       // buffer 'cur' ready; prior reads of cur^1 done

        if (kb < KBLK - 1)
            load_block(kb + 1, cur ^ 1);       // overlaps the compute below

        // fragment addresses rebuilt per K-block (short live ranges)
        const uint32_t so = cur * BUFB;
        uint32_t aaddr[2], baddr[2];
        {
            const int a_row  = lane & 15;
            const int a_coff = (lane >> 4) * 8;
            const int b_row  = ((lane >> 4) << 3) + (lane & 7);
            const int b_coff = ((lane >> 3) & 1) * 8;
            #pragma unroll
            for (int i = 0; i < 2; ++i)
                aaddr[i] = sb0 + so + ((wm * 32 + i * 16 + a_row) * LDH + a_coff) * 2;
            #pragma unroll
            for (int jp = 0; jp < 2; ++jp)
                baddr[jp] = sb0 + so + ABYT + ((wn * 32 + jp * 16 + b_row) * LDH + b_coff) * 2;
        }

        #pragma unroll
        for (int s = 0; s < 4; ++s) {          // K=64, 16 per MMA
            const uint32_t koff = s * 32;      // bytes (16 halves)
            uint32_t a[2][4], b[4][2];
            #pragma unroll
            for (int i = 0; i < 2; ++i)
                ldsm_x4(a[i][0], a[i][1], a[i][2], a[i][3], aaddr[i] + koff);
            #pragma unroll
            for (int jp = 0; jp < 2; ++jp)
                ldsm_x4(b[2 * jp][0], b[2 * jp][1], b[2 * jp + 1][0], b[2 * jp + 1][1],
                        baddr[jp] + koff);
            #pragma unroll
            for (int i = 0; i < 2; ++i)
                #pragma unroll
                for (int j = 0; j < 4; ++j) {
                    asm volatile(
                        "mma.sync.aligned.m16n8k16.row.col.f32.f16.f16.f32 "
                        "{%0,%1,%2,%3}, {%4,%5,%6,%7}, {%8,%9}, {%0,%1,%2,%3};\n"
                        : "+f"(acc[i][j][0]), "+f"(acc[i][j][1]),
                          "+f"(acc[i][j][2]), "+f"(acc[i][j][3])
                        : "r"(a[i][0]), "r"(a[i][1]), "r"(a[i][2]), "r"(a[i][3]),
                          "r"(b[j][0]), "r"(b[j][1]));
                }
        }
    }

    // ---- epilogue: bias add + float2 stores ----
    const int qr = lane >> 2, ql = lane & 3;
    const int n0 = rb * BLK;
    #pragma unroll
    for (int j = 0; j < 4; ++j) {
        const int col = n0 + wn * 32 + j * 8 + 2 * ql;
        const float2 bv = *(const float2*)(bias + col);
        #pragma unroll
        for (int i = 0; i < 2; ++i) {
            const int row = m0 + wm * 32 + i * 16 + qr;
            float2 v0 = { acc[i][j][0] + bv.x, acc[i][j][1] + bv.y };
            *(float2*)(out + (size_t)row * OUT_F + col) = v0;
            float2 v1 = { acc[i][j][2] + bv.x, acc[i][j][3] + bv.y };
            *(float2*)(out + (size_t)(row + 8) * OUT_F + col) = v1;
        }
    }
}

extern "C" void kernel_launch(void* const* d_in, const int* in_sizes, int n_in,
                              void* d_out, int out_size)
{
    const float* x       = (const float*)d_in[0];
    const float* weight  = (const float*)d_in[1];
    const float* bias    = (const float*)d_in[2];
    // d_in[3] = row_idx (deterministic repeat(arange(64),16)) — unused
    const int*   col_idx = (const int*)d_in[4];
    float* out = (float*)d_out;

    __half* xh_p; cudaGetSymbolAddress((void**)&xh_p, g_xh);
    __half* wh_p; cudaGetSymbolAddress((void**)&wh_p, g_wh);
    const int nx4 = (N_TOK * IN_F) / 4;
    const int nw4 = (BLK * KBLK * BLK * BLK) / 4;
    conv_all<<<(nx4 + nw4) / 256, 256>>>((const float4*)x, (const float4*)weight,
                                         (uint2*)xh_p, (uint2*)wh_p, nx4, nw4);

    cudaFuncSetAttribute(bsl_f16_kernel,
                         cudaFuncAttributeMaxDynamicSharedMemorySize, SMEM_BYTES);
    dim3 grid(OUT_F / BLK, N_TOK / TM);   // (64, 64); rb fastest -> x L2 reuse
    bsl_f16_kernel<<<grid, 256, SMEM_BYTES>>>(bias, col_idx, out);
}